// round 2
// baseline (speedup 1.0000x reference)
#include <cuda_runtime.h>
#include <cstdint>

#define D 64
#define MAX_NODES 100000

// Scratch for aggregated neighborhood features (25.6 MB).
__device__ float g_neigh[MAX_NODES * D];
// 1 if edge index arrays are int64, 0 if int32.
__device__ int g_idx64;

// ---------------------------------------------------------------------------
// K-1: detect index dtype. If int64 (values < 2^31), every odd 32-bit word
// of the buffer is zero. Check 1024 edges' worth of odd words.
// ---------------------------------------------------------------------------
__global__ void detect_dtype_kernel(const unsigned int* __restrict__ esrc_w,
                                    int n_edges) {
    __shared__ int s_ok;
    if (threadIdx.x == 0) s_ok = 1;
    __syncthreads();
    int n_check = n_edges < 1024 ? n_edges : 1024;
    for (int i = threadIdx.x; i < n_check; i += blockDim.x) {
        if (esrc_w[2 * i + 1] != 0u) atomicAnd(&s_ok, 0);
    }
    __syncthreads();
    if (threadIdx.x == 0) g_idx64 = s_ok;
}

// ---------------------------------------------------------------------------
// K0: zero the neigh scratch.
// ---------------------------------------------------------------------------
__global__ void zero_neigh_kernel(int n_float4) {
    int i = blockIdx.x * blockDim.x + threadIdx.x;
    float4 z = make_float4(0.f, 0.f, 0.f, 0.f);
    float4* p = reinterpret_cast<float4*>(g_neigh);
    for (; i < n_float4; i += gridDim.x * blockDim.x) p[i] = z;
}

// ---------------------------------------------------------------------------
// K1: per-edge SDDMM + scatter. 16 lanes per edge, float4 per lane.
// ---------------------------------------------------------------------------
__global__ void edge_kernel(const float* __restrict__ feat,
                            const void* __restrict__ edge_src,
                            const void* __restrict__ edge_dst,
                            int n_edges, int n_nodes) {
    int t = blockIdx.x * blockDim.x + threadIdx.x;
    int e = t >> 4;
    int lane = t & 15;
    bool valid = (e < n_edges);
    int ec = valid ? e : (n_edges - 1);   // clamp so shfl group stays converged

    long long s, d;
    if (g_idx64) {
        s = ((const long long*)edge_src)[ec];
        d = ((const long long*)edge_dst)[ec];
    } else {
        s = ((const int*)edge_src)[ec];
        d = ((const int*)edge_dst)[ec];
    }
    // Safety clamp — never crash on a dtype surprise; correctness check reports it.
    if (s < 0) s = 0; if (s >= n_nodes) s = n_nodes - 1;
    if (d < 0) d = 0; if (d >= n_nodes) d = n_nodes - 1;

    const float4 hs = *reinterpret_cast<const float4*>(feat + (size_t)s * D + lane * 4);
    const float4 hd = *reinterpret_cast<const float4*>(feat + (size_t)d * D + lane * 4);

    float p = hs.x * hd.x + hs.y * hd.y + hs.z * hd.z + hs.w * hd.w;
    p += __shfl_xor_sync(0xffffffffu, p, 8);
    p += __shfl_xor_sync(0xffffffffu, p, 4);
    p += __shfl_xor_sync(0xffffffffu, p, 2);
    p += __shfl_xor_sync(0xffffffffu, p, 1);

    if (valid) {
        float4 m;
        m.x = hs.x * p; m.y = hs.y * p; m.z = hs.z * p; m.w = hs.w * p;
        float* dst = g_neigh + (size_t)d * D + lane * 4;
        asm volatile("red.global.add.v4.f32 [%0], {%1, %2, %3, %4};"
                     :: "l"(dst), "f"(m.x), "f"(m.y), "f"(m.z), "f"(m.w)
                     : "memory");
    }
}

// ---------------------------------------------------------------------------
// K2: out = neigh @ W.T.  W is [64, 64] row-major.
// Block (16,16): ty = row in 16-row tile, tx = float4 of output cols.
// ---------------------------------------------------------------------------
__global__ void gemm_kernel(const float* __restrict__ W,
                            float* __restrict__ out,
                            int n_rows) {
    __shared__ float sWt[D][D];        // [k][o] (W transposed)
    __shared__ float sN[16][D];

    int tid = threadIdx.y * 16 + threadIdx.x;

    #pragma unroll
    for (int i = tid; i < D * D; i += 256) {
        int o = i >> 6;
        int k = i & 63;
        sWt[k][o] = W[i];
    }

    int row0 = blockIdx.x * 16;
    {
        int r = tid >> 4;
        int c4 = tid & 15;
        int row = row0 + r;
        float4 v = make_float4(0.f, 0.f, 0.f, 0.f);
        if (row < n_rows)
            v = *reinterpret_cast<const float4*>(g_neigh + (size_t)row * D + c4 * 4);
        *reinterpret_cast<float4*>(&sN[r][c4 * 4]) = v;
    }
    __syncthreads();

    int row = row0 + threadIdx.y;
    if (row < n_rows) {
        int c = threadIdx.x * 4;
        float4 acc = make_float4(0.f, 0.f, 0.f, 0.f);
        #pragma unroll
        for (int k = 0; k < D; k++) {
            float nb = sN[threadIdx.y][k];
            const float4 w = *reinterpret_cast<const float4*>(&sWt[k][c]);
            acc.x += nb * w.x;
            acc.y += nb * w.y;
            acc.z += nb * w.z;
            acc.w += nb * w.w;
        }
        *reinterpret_cast<float4*>(out + (size_t)row * D + c) = acc;
    }
}

// ---------------------------------------------------------------------------
extern "C" void kernel_launch(void* const* d_in, const int* in_sizes, int n_in,
                              void* d_out, int out_size) {
    const float* feat = (const float*)d_in[0];
    const void*  esrc = d_in[1];
    const void*  edst = d_in[2];
    const float* W    = (const float*)d_in[3];
    float*       out  = (float*)d_out;

    int n_nodes = in_sizes[0] / D;
    int n_edges = in_sizes[1];

    detect_dtype_kernel<<<1, 256>>>((const unsigned int*)esrc, n_edges);

    int n4 = n_nodes * D / 4;
    int zgrid = (n4 + 511) / 512;
    if (zgrid > 4096) zgrid = 4096;
    zero_neigh_kernel<<<zgrid, 512>>>(n4);

    int egrid = (n_edges + 15) / 16;
    edge_kernel<<<egrid, 256>>>(feat, esrc, edst, n_edges, n_nodes);

    int ggrid = (n_nodes + 15) / 16;
    gemm_kernel<<<ggrid, dim3(16, 16)>>>(W, out, n_nodes);
}

// round 3
// speedup vs baseline: 1.8015x; 1.8015x over previous
#include <cuda_runtime.h>
#include <cstdint>

#define D 64
#define MAX_NODES 100000
#define GR 64          // rows per GEMM block
#define SPAD 68        // smem row stride (floats): bank-shift 4, float4-aligned

__device__ float g_neigh[MAX_NODES * D];
__device__ int g_idx64;

// ---------------------------------------------------------------------------
// detect index dtype: int64 buffers (values < 2^31) have all odd words zero.
// ---------------------------------------------------------------------------
__global__ void detect_dtype_kernel(const unsigned int* __restrict__ esrc_w,
                                    int n_edges) {
    __shared__ int s_ok;
    if (threadIdx.x == 0) s_ok = 1;
    __syncthreads();
    int n_check = n_edges < 1024 ? n_edges : 1024;
    for (int i = threadIdx.x; i < n_check; i += blockDim.x) {
        if (esrc_w[2 * i + 1] != 0u) atomicAnd(&s_ok, 0);
    }
    __syncthreads();
    if (threadIdx.x == 0) g_idx64 = s_ok;
}

// ---------------------------------------------------------------------------
__global__ void zero_neigh_kernel(int n_float4) {
    int i = blockIdx.x * blockDim.x + threadIdx.x;
    float4 z = make_float4(0.f, 0.f, 0.f, 0.f);
    float4* p = reinterpret_cast<float4*>(g_neigh);
    for (; i < n_float4; i += gridDim.x * blockDim.x) p[i] = z;
}

// ---------------------------------------------------------------------------
// edge kernel: 16 lanes per edge, float4 per lane.
// ---------------------------------------------------------------------------
__global__ void edge_kernel(const float* __restrict__ feat,
                            const void* __restrict__ edge_src,
                            const void* __restrict__ edge_dst,
                            int n_edges, int n_nodes) {
    int t = blockIdx.x * blockDim.x + threadIdx.x;
    int e = t >> 4;
    int lane = t & 15;
    bool valid = (e < n_edges);
    int ec = valid ? e : (n_edges - 1);

    long long s, d;
    if (g_idx64) {
        s = ((const long long*)edge_src)[ec];
        d = ((const long long*)edge_dst)[ec];
    } else {
        s = ((const int*)edge_src)[ec];
        d = ((const int*)edge_dst)[ec];
    }
    if (s < 0) s = 0; if (s >= n_nodes) s = n_nodes - 1;
    if (d < 0) d = 0; if (d >= n_nodes) d = n_nodes - 1;

    const float4 hs = *reinterpret_cast<const float4*>(feat + (size_t)s * D + lane * 4);
    const float4 hd = *reinterpret_cast<const float4*>(feat + (size_t)d * D + lane * 4);

    float p = hs.x * hd.x + hs.y * hd.y + hs.z * hd.z + hs.w * hd.w;
    p += __shfl_xor_sync(0xffffffffu, p, 8);
    p += __shfl_xor_sync(0xffffffffu, p, 4);
    p += __shfl_xor_sync(0xffffffffu, p, 2);
    p += __shfl_xor_sync(0xffffffffu, p, 1);

    if (valid) {
        float4 m;
        m.x = hs.x * p; m.y = hs.y * p; m.z = hs.z * p; m.w = hs.w * p;
        float* dst = g_neigh + (size_t)d * D + lane * 4;
        asm volatile("red.global.add.v4.f32 [%0], {%1, %2, %3, %4};"
                     :: "l"(dst), "f"(m.x), "f"(m.y), "f"(m.z), "f"(m.w)
                     : "memory");
    }
}

// ---------------------------------------------------------------------------
// GEMM: out = neigh @ W.T.   64 rows/block, 256 threads.
// Thread (tx 0..15, ty 0..15) computes 4 rows (ty + 16j) x 4 cols (tx*4..+3).
// k unrolled by 4 with LDS.128 on both sN rows and sWt rows.
// ---------------------------------------------------------------------------
__global__ __launch_bounds__(256) void gemm_kernel(const float* __restrict__ W,
                                                   float* __restrict__ out,
                                                   int n_rows) {
    __shared__ float sWt[D][SPAD];   // [k][o]  (W transposed, padded)
    __shared__ float sN[GR][SPAD];   // neigh rows, padded

    int tid = threadIdx.x;
    int tx = tid & 15;
    int ty = tid >> 4;

    // Load W (coalesced LDG) and store transposed: sWt[k][o] = W[o*64+k].
    // STS bank = (4k + o) % 32 -> 4-way conflict, one-time cost.
    #pragma unroll
    for (int it = 0; it < 16; it++) {
        int idx = tid + 256 * it;
        int o = idx >> 6;
        int k = idx & 63;
        sWt[k][o] = W[idx];
    }

    int row0 = blockIdx.x * GR;
    // Load 64 neigh rows: 1024 float4, 4 per thread, coalesced.
    #pragma unroll
    for (int it = 0; it < 4; it++) {
        int idx = tid + 256 * it;    // float4 index
        int r = idx >> 4;
        int c4 = idx & 15;
        int row = row0 + r;
        float4 v = make_float4(0.f, 0.f, 0.f, 0.f);
        if (row < n_rows)
            v = *reinterpret_cast<const float4*>(g_neigh + (size_t)row * D + c4 * 4);
        *reinterpret_cast<float4*>(&sN[r][c4 * 4]) = v;
    }
    __syncthreads();

    float4 acc[4];
    #pragma unroll
    for (int j = 0; j < 4; j++) acc[j] = make_float4(0.f, 0.f, 0.f, 0.f);

    int c = tx * 4;
    #pragma unroll
    for (int k4 = 0; k4 < D / 4; k4++) {
        int k = k4 * 4;
        const float4 w0 = *reinterpret_cast<const float4*>(&sWt[k + 0][c]);
        const float4 w1 = *reinterpret_cast<const float4*>(&sWt[k + 1][c]);
        const float4 w2 = *reinterpret_cast<const float4*>(&sWt[k + 2][c]);
        const float4 w3 = *reinterpret_cast<const float4*>(&sWt[k + 3][c]);
        #pragma unroll
        for (int j = 0; j < 4; j++) {
            const float4 nb = *reinterpret_cast<const float4*>(&sN[ty + 16 * j][k]);
            acc[j].x += nb.x * w0.x; acc[j].y += nb.x * w0.y;
            acc[j].z += nb.x * w0.z; acc[j].w += nb.x * w0.w;
            acc[j].x += nb.y * w1.x; acc[j].y += nb.y * w1.y;
            acc[j].z += nb.y * w1.z; acc[j].w += nb.y * w1.w;
            acc[j].x += nb.z * w2.x; acc[j].y += nb.z * w2.y;
            acc[j].z += nb.z * w2.z; acc[j].w += nb.z * w2.w;
            acc[j].x += nb.w * w3.x; acc[j].y += nb.w * w3.y;
            acc[j].z += nb.w * w3.z; acc[j].w += nb.w * w3.w;
        }
    }

    #pragma unroll
    for (int j = 0; j < 4; j++) {
        int row = row0 + ty + 16 * j;
        if (row < n_rows)
            *reinterpret_cast<float4*>(out + (size_t)row * D + c) = acc[j];
    }
}

// ---------------------------------------------------------------------------
extern "C" void kernel_launch(void* const* d_in, const int* in_sizes, int n_in,
                              void* d_out, int out_size) {
    const float* feat = (const float*)d_in[0];
    const void*  esrc = d_in[1];
    const void*  edst = d_in[2];
    const float* W    = (const float*)d_in[3];
    float*       out  = (float*)d_out;

    int n_nodes = in_sizes[0] / D;
    int n_edges = in_sizes[1];

    detect_dtype_kernel<<<1, 256>>>((const unsigned int*)esrc, n_edges);

    int n4 = n_nodes * D / 4;
    int zgrid = (n4 + 511) / 512;
    if (zgrid > 4096) zgrid = 4096;
    zero_neigh_kernel<<<zgrid, 512>>>(n4);

    int egrid = (n_edges + 15) / 16;
    edge_kernel<<<egrid, 256>>>(feat, esrc, edst, n_edges, n_nodes);

    int ggrid = (n_nodes + GR - 1) / GR;
    gemm_kernel<<<ggrid, 256>>>(W, out, n_nodes);
}

// round 4
// speedup vs baseline: 2.0298x; 1.1268x over previous
#include <cuda_runtime.h>
#include <cstdint>

#define D 64
#define MAX_NODES 100000
#define MAX_EDGES 1600000
#define GR 64          // rows per GEMM block
#define SPAD 68        // smem row stride (floats)

__device__ float g_neigh[MAX_NODES * D];
__device__ int   g_idx64;
__device__ int   g_cnt[MAX_NODES];       // in-degree histogram
__device__ int   g_start[MAX_NODES];     // exclusive prefix (CSR row offsets)
__device__ int   g_pos[MAX_NODES];       // scatter cursors
__device__ int   g_srcsorted[MAX_EDGES]; // src indices grouped by dst
__device__ int   g_bsum[128];            // block sums for 2-level scan

// ---------------------------------------------------------------------------
// detect index dtype: int64 buffers (values < 2^31) have all odd words zero.
// ---------------------------------------------------------------------------
__global__ void detect_dtype_kernel(const unsigned int* __restrict__ esrc_w,
                                    int n_edges) {
    __shared__ int s_ok;
    if (threadIdx.x == 0) s_ok = 1;
    __syncthreads();
    int n_check = n_edges < 1024 ? n_edges : 1024;
    for (int i = threadIdx.x; i < n_check; i += blockDim.x) {
        if (esrc_w[2 * i + 1] != 0u) atomicAnd(&s_ok, 0);
    }
    __syncthreads();
    if (threadIdx.x == 0) g_idx64 = s_ok;
}

__device__ __forceinline__ int load_idx(const void* p, int e, int n_nodes) {
    long long v = g_idx64 ? ((const long long*)p)[e] : (long long)((const int*)p)[e];
    if (v < 0) v = 0;
    if (v >= n_nodes) v = n_nodes - 1;
    return (int)v;
}

// ---------------------------------------------------------------------------
__global__ void zero_cnt_kernel(int n) {
    int i = blockIdx.x * blockDim.x + threadIdx.x;
    if (i < n) g_cnt[i] = 0;
}

__global__ void hist_kernel(const void* __restrict__ edge_dst,
                            int n_edges, int n_nodes) {
    int e = blockIdx.x * blockDim.x + threadIdx.x;
    if (e >= n_edges) return;
    int d = load_idx(edge_dst, e, n_nodes);
    asm volatile("red.global.add.u32 [%0], %1;"
                 :: "l"(&g_cnt[d]), "r"(1) : "memory");
}

// ---------------------------------------------------------------------------
// Two-level exclusive scan of g_cnt -> g_start (and g_pos copy).
// ---------------------------------------------------------------------------
__global__ void scanA_kernel(int n) {
    __shared__ int s[1024];
    int gid = blockIdx.x * 1024 + threadIdx.x;
    int v = (gid < n) ? g_cnt[gid] : 0;
    s[threadIdx.x] = v;
    __syncthreads();
    #pragma unroll
    for (int off = 1; off < 1024; off <<= 1) {
        int t = (threadIdx.x >= off) ? s[threadIdx.x - off] : 0;
        __syncthreads();
        s[threadIdx.x] += t;
        __syncthreads();
    }
    if (gid < n) g_start[gid] = s[threadIdx.x] - v;     // exclusive within block
    if (threadIdx.x == 1023) g_bsum[blockIdx.x] = s[1023];
}

__global__ void scanB_kernel(int nb) {   // nb <= 128, single block of 128
    __shared__ int s[128];
    int v = (threadIdx.x < nb) ? g_bsum[threadIdx.x] : 0;
    s[threadIdx.x] = v;
    __syncthreads();
    #pragma unroll
    for (int off = 1; off < 128; off <<= 1) {
        int t = (threadIdx.x >= off) ? s[threadIdx.x - off] : 0;
        __syncthreads();
        s[threadIdx.x] += t;
        __syncthreads();
    }
    g_bsum[threadIdx.x] = s[threadIdx.x] - v;           // exclusive block sums
}

__global__ void scanC_kernel(int n) {
    int gid = blockIdx.x * 1024 + threadIdx.x;
    if (gid < n) {
        int o = g_start[gid] + g_bsum[gid >> 10];
        g_start[gid] = o;
        g_pos[gid] = o;
    }
}

// ---------------------------------------------------------------------------
// Scatter: bucket src indices by dst.
// ---------------------------------------------------------------------------
__global__ void scatter_kernel(const void* __restrict__ edge_src,
                               const void* __restrict__ edge_dst,
                               int n_edges, int n_nodes) {
    int e = blockIdx.x * blockDim.x + threadIdx.x;
    if (e >= n_edges) return;
    int s = load_idx(edge_src, e, n_nodes);
    int d = load_idx(edge_dst, e, n_nodes);
    int pos = atomicAdd(&g_pos[d], 1);
    g_srcsorted[pos] = s;
}

// ---------------------------------------------------------------------------
// Fused SDDMM + SpMM, gather form: one warp per dst node.
// Each lane owns 2 floats (float2). Dot via 5-step shfl butterfly.
// neigh row written exactly once -> no atomics, no pre-zero.
// ---------------------------------------------------------------------------
__global__ __launch_bounds__(256) void spmm_gather_kernel(
        const float* __restrict__ feat, int n_nodes) {
    int w = (blockIdx.x * blockDim.x + threadIdx.x) >> 5;
    int lane = threadIdx.x & 31;
    if (w >= n_nodes) return;

    int start = g_start[w];
    int end = start + g_cnt[w];

    const float2 hd = *reinterpret_cast<const float2*>(feat + (size_t)w * D + lane * 2);
    float ax = 0.f, ay = 0.f;

    int i = start;
    for (; i + 1 < end; i += 2) {
        int s0 = g_srcsorted[i];
        int s1 = g_srcsorted[i + 1];
        const float2 h0 = *reinterpret_cast<const float2*>(feat + (size_t)s0 * D + lane * 2);
        const float2 h1 = *reinterpret_cast<const float2*>(feat + (size_t)s1 * D + lane * 2);
        float p0 = h0.x * hd.x + h0.y * hd.y;
        float p1 = h1.x * hd.x + h1.y * hd.y;
        p0 += __shfl_xor_sync(0xffffffffu, p0, 16);
        p1 += __shfl_xor_sync(0xffffffffu, p1, 16);
        p0 += __shfl_xor_sync(0xffffffffu, p0, 8);
        p1 += __shfl_xor_sync(0xffffffffu, p1, 8);
        p0 += __shfl_xor_sync(0xffffffffu, p0, 4);
        p1 += __shfl_xor_sync(0xffffffffu, p1, 4);
        p0 += __shfl_xor_sync(0xffffffffu, p0, 2);
        p1 += __shfl_xor_sync(0xffffffffu, p1, 2);
        p0 += __shfl_xor_sync(0xffffffffu, p0, 1);
        p1 += __shfl_xor_sync(0xffffffffu, p1, 1);
        ax += h0.x * p0; ay += h0.y * p0;
        ax += h1.x * p1; ay += h1.y * p1;
    }
    if (i < end) {
        int s0 = g_srcsorted[i];
        const float2 h0 = *reinterpret_cast<const float2*>(feat + (size_t)s0 * D + lane * 2);
        float p0 = h0.x * hd.x + h0.y * hd.y;
        p0 += __shfl_xor_sync(0xffffffffu, p0, 16);
        p0 += __shfl_xor_sync(0xffffffffu, p0, 8);
        p0 += __shfl_xor_sync(0xffffffffu, p0, 4);
        p0 += __shfl_xor_sync(0xffffffffu, p0, 2);
        p0 += __shfl_xor_sync(0xffffffffu, p0, 1);
        ax += h0.x * p0; ay += h0.y * p0;
    }

    float2 r; r.x = ax; r.y = ay;
    *reinterpret_cast<float2*>(g_neigh + (size_t)w * D + lane * 2) = r;
}

// ---------------------------------------------------------------------------
// GEMM: out = neigh @ W.T (unchanged from R3 — 27.5us, known good).
// ---------------------------------------------------------------------------
__global__ __launch_bounds__(256) void gemm_kernel(const float* __restrict__ W,
                                                   float* __restrict__ out,
                                                   int n_rows) {
    __shared__ float sWt[D][SPAD];
    __shared__ float sN[GR][SPAD];

    int tid = threadIdx.x;
    int tx = tid & 15;
    int ty = tid >> 4;

    #pragma unroll
    for (int it = 0; it < 16; it++) {
        int idx = tid + 256 * it;
        int o = idx >> 6;
        int k = idx & 63;
        sWt[k][o] = W[idx];
    }

    int row0 = blockIdx.x * GR;
    #pragma unroll
    for (int it = 0; it < 4; it++) {
        int idx = tid + 256 * it;
        int r = idx >> 4;
        int c4 = idx & 15;
        int row = row0 + r;
        float4 v = make_float4(0.f, 0.f, 0.f, 0.f);
        if (row < n_rows)
            v = *reinterpret_cast<const float4*>(g_neigh + (size_t)row * D + c4 * 4);
        *reinterpret_cast<float4*>(&sN[r][c4 * 4]) = v;
    }
    __syncthreads();

    float4 acc[4];
    #pragma unroll
    for (int j = 0; j < 4; j++) acc[j] = make_float4(0.f, 0.f, 0.f, 0.f);

    int c = tx * 4;
    #pragma unroll
    for (int k4 = 0; k4 < D / 4; k4++) {
        int k = k4 * 4;
        const float4 w0 = *reinterpret_cast<const float4*>(&sWt[k + 0][c]);
        const float4 w1 = *reinterpret_cast<const float4*>(&sWt[k + 1][c]);
        const float4 w2 = *reinterpret_cast<const float4*>(&sWt[k + 2][c]);
        const float4 w3 = *reinterpret_cast<const float4*>(&sWt[k + 3][c]);
        #pragma unroll
        for (int j = 0; j < 4; j++) {
            const float4 nb = *reinterpret_cast<const float4*>(&sN[ty + 16 * j][k]);
            acc[j].x += nb.x * w0.x; acc[j].y += nb.x * w0.y;
            acc[j].z += nb.x * w0.z; acc[j].w += nb.x * w0.w;
            acc[j].x += nb.y * w1.x; acc[j].y += nb.y * w1.y;
            acc[j].z += nb.y * w1.z; acc[j].w += nb.y * w1.w;
            acc[j].x += nb.z * w2.x; acc[j].y += nb.z * w2.y;
            acc[j].z += nb.z * w2.z; acc[j].w += nb.z * w2.w;
            acc[j].x += nb.w * w3.x; acc[j].y += nb.w * w3.y;
            acc[j].z += nb.w * w3.z; acc[j].w += nb.w * w3.w;
        }
    }

    #pragma unroll
    for (int j = 0; j < 4; j++) {
        int row = row0 + ty + 16 * j;
        if (row < n_rows)
            *reinterpret_cast<float4*>(out + (size_t)row * D + c) = acc[j];
    }
}

// ---------------------------------------------------------------------------
extern "C" void kernel_launch(void* const* d_in, const int* in_sizes, int n_in,
                              void* d_out, int out_size) {
    const float* feat = (const float*)d_in[0];
    const void*  esrc = d_in[1];
    const void*  edst = d_in[2];
    const float* W    = (const float*)d_in[3];
    float*       out  = (float*)d_out;

    int n_nodes = in_sizes[0] / D;
    int n_edges = in_sizes[1];

    detect_dtype_kernel<<<1, 256>>>((const unsigned int*)esrc, n_edges);

    zero_cnt_kernel<<<(n_nodes + 511) / 512, 512>>>(n_nodes);
    hist_kernel<<<(n_edges + 511) / 512, 512>>>(edst, n_edges, n_nodes);

    int nblk = (n_nodes + 1023) / 1024;       // <= 128
    scanA_kernel<<<nblk, 1024>>>(n_nodes);
    scanB_kernel<<<1, 128>>>(nblk);
    scanC_kernel<<<nblk, 1024>>>(n_nodes);

    scatter_kernel<<<(n_edges + 255) / 256, 256>>>(esrc, edst, n_edges, n_nodes);

    spmm_gather_kernel<<<(n_nodes * 32 + 255) / 256, 256>>>(feat, n_nodes);

    gemm_kernel<<<(n_nodes + GR - 1) / GR, 256>>>(W, out, n_nodes);
}

// round 5
// speedup vs baseline: 2.1349x; 1.0518x over previous
#include <cuda_runtime.h>
#include <cstdint>

#define D 64
#define MAX_NODES 100000
#define MAX_EDGES 1600000
#define GR 64          // rows per GEMM block
#define SPAD 68        // smem row stride (floats)

__device__ float g_neigh[MAX_NODES * D];
__device__ int   g_idx64;
__device__ int   g_cnt[MAX_NODES];       // in-degree histogram
__device__ int   g_start[MAX_NODES];     // exclusive prefix (CSR row offsets)
__device__ int   g_pos[MAX_NODES];       // scatter cursors
__device__ int   g_srcsorted[MAX_EDGES]; // src indices grouped by dst
__device__ int   g_bsum[128];            // block sums for 2-level scan

// ---------------------------------------------------------------------------
// detect index dtype: int64 buffers (values < 2^31) have all odd words zero.
// ---------------------------------------------------------------------------
__global__ void detect_dtype_kernel(const unsigned int* __restrict__ esrc_w,
                                    int n_edges) {
    __shared__ int s_ok;
    if (threadIdx.x == 0) s_ok = 1;
    __syncthreads();
    int n_check = n_edges < 1024 ? n_edges : 1024;
    for (int i = threadIdx.x; i < n_check; i += blockDim.x) {
        if (esrc_w[2 * i + 1] != 0u) atomicAnd(&s_ok, 0);
    }
    __syncthreads();
    if (threadIdx.x == 0) g_idx64 = s_ok;
}

__device__ __forceinline__ int load_idx(const void* p, int e, int n_nodes) {
    int v;
    if (g_idx64) v = (int)((const long long*)p)[e];
    else         v = ((const int*)p)[e];
    if (v < 0) v = 0;
    if (v >= n_nodes) v = n_nodes - 1;
    return v;
}

// ---------------------------------------------------------------------------
__global__ void zero_cnt_kernel(int n) {
    int i = blockIdx.x * blockDim.x + threadIdx.x;
    if (i < n) g_cnt[i] = 0;
}

__global__ void hist_kernel(const void* __restrict__ edge_dst,
                            int n_edges, int n_nodes) {
    int e = blockIdx.x * blockDim.x + threadIdx.x;
    if (e >= n_edges) return;
    int d = load_idx(edge_dst, e, n_nodes);
    asm volatile("red.global.add.u32 [%0], %1;"
                 :: "l"(&g_cnt[d]), "r"(1) : "memory");
}

// ---------------------------------------------------------------------------
// Shfl-based block scan (2 barriers instead of 20).
// ---------------------------------------------------------------------------
__device__ __forceinline__ int warp_incl_scan(int x, int lane) {
    #pragma unroll
    for (int off = 1; off < 32; off <<= 1) {
        int t = __shfl_up_sync(0xffffffffu, x, off);
        if (lane >= off) x += t;
    }
    return x;
}

__global__ void scanA_kernel(int n) {
    __shared__ int wsum[32];
    int gid = blockIdx.x * 1024 + threadIdx.x;
    int lane = threadIdx.x & 31;
    int wid = threadIdx.x >> 5;
    int v = (gid < n) ? g_cnt[gid] : 0;
    int x = warp_incl_scan(v, lane);
    if (lane == 31) wsum[wid] = x;
    __syncthreads();
    if (wid == 0) wsum[lane] = warp_incl_scan(wsum[lane], lane);
    __syncthreads();
    int incl = x + (wid > 0 ? wsum[wid - 1] : 0);
    if (gid < n) g_start[gid] = incl - v;            // exclusive within block
    if (threadIdx.x == 1023) g_bsum[blockIdx.x] = incl;
}

__global__ void scanB_kernel(int nb) {   // nb <= 128, single block of 128
    __shared__ int wsum[4];
    int lane = threadIdx.x & 31;
    int wid = threadIdx.x >> 5;
    int v = (threadIdx.x < nb) ? g_bsum[threadIdx.x] : 0;
    int x = warp_incl_scan(v, lane);
    if (lane == 31) wsum[wid] = x;
    __syncthreads();
    int pre = 0;
    #pragma unroll
    for (int w = 0; w < 4; w++) if (w < wid) pre += wsum[w];
    g_bsum[threadIdx.x] = x + pre - v;               // exclusive block sums
}

__global__ void scanC_kernel(int n) {
    int gid = blockIdx.x * 1024 + threadIdx.x;
    if (gid < n) {
        int o = g_start[gid] + g_bsum[gid >> 10];
        g_start[gid] = o;
        g_pos[gid] = o;
    }
}

// ---------------------------------------------------------------------------
__global__ void scatter_kernel(const void* __restrict__ edge_src,
                               const void* __restrict__ edge_dst,
                               int n_edges, int n_nodes) {
    int e = blockIdx.x * blockDim.x + threadIdx.x;
    if (e >= n_edges) return;
    int s = load_idx(edge_src, e, n_nodes);
    int d = load_idx(edge_dst, e, n_nodes);
    int pos = atomicAdd(&g_pos[d], 1);
    g_srcsorted[pos] = s;
}

// ---------------------------------------------------------------------------
// Fused SDDMM + SpMM gather: 16-lane group per dst node (2 nodes per warp).
// Each lane owns a float4 (lane*4 of 64). Dot via 4-step shfl butterfly
// within the half-warp (per-half mask; halves run independent trip counts).
// ---------------------------------------------------------------------------
__global__ __launch_bounds__(256) void spmm_gather_kernel(
        const float* __restrict__ feat, int n_nodes) {
    int g = (blockIdx.x * blockDim.x + threadIdx.x) >> 4;   // node id
    int lane = threadIdx.x & 15;
    unsigned hm = 0xFFFFu << (threadIdx.x & 16);            // own-half mask
    if (g >= n_nodes) return;

    int start = g_start[g];
    int end = start + g_cnt[g];

    const float4 hd = *reinterpret_cast<const float4*>(feat + (size_t)g * D + lane * 4);
    float4 acc = make_float4(0.f, 0.f, 0.f, 0.f);

    int i = start;
    for (; i + 1 < end; i += 2) {
        int s0 = g_srcsorted[i];
        int s1 = g_srcsorted[i + 1];
        const float4 h0 = *reinterpret_cast<const float4*>(feat + (size_t)s0 * D + lane * 4);
        const float4 h1 = *reinterpret_cast<const float4*>(feat + (size_t)s1 * D + lane * 4);
        float p0 = h0.x * hd.x + h0.y * hd.y + h0.z * hd.z + h0.w * hd.w;
        float p1 = h1.x * hd.x + h1.y * hd.y + h1.z * hd.z + h1.w * hd.w;
        p0 += __shfl_xor_sync(hm, p0, 8);
        p1 += __shfl_xor_sync(hm, p1, 8);
        p0 += __shfl_xor_sync(hm, p0, 4);
        p1 += __shfl_xor_sync(hm, p1, 4);
        p0 += __shfl_xor_sync(hm, p0, 2);
        p1 += __shfl_xor_sync(hm, p1, 2);
        p0 += __shfl_xor_sync(hm, p0, 1);
        p1 += __shfl_xor_sync(hm, p1, 1);
        acc.x += h0.x * p0 + h1.x * p1;
        acc.y += h0.y * p0 + h1.y * p1;
        acc.z += h0.z * p0 + h1.z * p1;
        acc.w += h0.w * p0 + h1.w * p1;
    }
    if (i < end) {
        int s0 = g_srcsorted[i];
        const float4 h0 = *reinterpret_cast<const float4*>(feat + (size_t)s0 * D + lane * 4);
        float p0 = h0.x * hd.x + h0.y * hd.y + h0.z * hd.z + h0.w * hd.w;
        p0 += __shfl_xor_sync(hm, p0, 8);
        p0 += __shfl_xor_sync(hm, p0, 4);
        p0 += __shfl_xor_sync(hm, p0, 2);
        p0 += __shfl_xor_sync(hm, p0, 1);
        acc.x += h0.x * p0;
        acc.y += h0.y * p0;
        acc.z += h0.z * p0;
        acc.w += h0.w * p0;
    }

    *reinterpret_cast<float4*>(g_neigh + (size_t)g * D + lane * 4) = acc;
}

// ---------------------------------------------------------------------------
// GEMM: out = neigh @ W.T (unchanged — at scalar FFMA floor).
// ---------------------------------------------------------------------------
__global__ __launch_bounds__(256) void gemm_kernel(const float* __restrict__ W,
                                                   float* __restrict__ out,
                                                   int n_rows) {
    __shared__ float sWt[D][SPAD];
    __shared__ float sN[GR][SPAD];

    int tid = threadIdx.x;
    int tx = tid & 15;
    int ty = tid >> 4;

    #pragma unroll
    for (int it = 0; it < 16; it++) {
        int idx = tid + 256 * it;
        int o = idx >> 6;
        int k = idx & 63;
        sWt[k][o] = W[idx];
    }

    int row0 = blockIdx.x * GR;
    #pragma unroll
    for (int it = 0; it < 4; it++) {
        int idx = tid + 256 * it;
        int r = idx >> 4;
        int c4 = idx & 15;
        int row = row0 + r;
        float4 v = make_float4(0.f, 0.f, 0.f, 0.f);
        if (row < n_rows)
            v = *reinterpret_cast<const float4*>(g_neigh + (size_t)row * D + c4 * 4);
        *reinterpret_cast<float4*>(&sN[r][c4 * 4]) = v;
    }
    __syncthreads();

    float4 acc[4];
    #pragma unroll
    for (int j = 0; j < 4; j++) acc[j] = make_float4(0.f, 0.f, 0.f, 0.f);

    int c = tx * 4;
    #pragma unroll
    for (int k4 = 0; k4 < D / 4; k4++) {
        int k = k4 * 4;
        const float4 w0 = *reinterpret_cast<const float4*>(&sWt[k + 0][c]);
        const float4 w1 = *reinterpret_cast<const float4*>(&sWt[k + 1][c]);
        const float4 w2 = *reinterpret_cast<const float4*>(&sWt[k + 2][c]);
        const float4 w3 = *reinterpret_cast<const float4*>(&sWt[k + 3][c]);
        #pragma unroll
        for (int j = 0; j < 4; j++) {
            const float4 nb = *reinterpret_cast<const float4*>(&sN[ty + 16 * j][k]);
            acc[j].x += nb.x * w0.x; acc[j].y += nb.x * w0.y;
            acc[j].z += nb.x * w0.z; acc[j].w += nb.x * w0.w;
            acc[j].x += nb.y * w1.x; acc[j].y += nb.y * w1.y;
            acc[j].z += nb.y * w1.z; acc[j].w += nb.y * w1.w;
            acc[j].x += nb.z * w2.x; acc[j].y += nb.z * w2.y;
            acc[j].z += nb.z * w2.z; acc[j].w += nb.z * w2.w;
            acc[j].x += nb.w * w3.x; acc[j].y += nb.w * w3.y;
            acc[j].z += nb.w * w3.z; acc[j].w += nb.w * w3.w;
        }
    }

    #pragma unroll
    for (int j = 0; j < 4; j++) {
        int row = row0 + ty + 16 * j;
        if (row < n_rows)
            *reinterpret_cast<float4*>(out + (size_t)row * D + c) = acc[j];
    }
}

// ---------------------------------------------------------------------------
extern "C" void kernel_launch(void* const* d_in, const int* in_sizes, int n_in,
                              void* d_out, int out_size) {
    const float* feat = (const float*)d_in[0];
    const void*  esrc = d_in[1];
    const void*  edst = d_in[2];
    const float* W    = (const float*)d_in[3];
    float*       out  = (float*)d_out;

    int n_nodes = in_sizes[0] / D;
    int n_edges = in_sizes[1];

    detect_dtype_kernel<<<1, 256>>>((const unsigned int*)esrc, n_edges);

    zero_cnt_kernel<<<(n_nodes + 511) / 512, 512>>>(n_nodes);
    hist_kernel<<<(n_edges + 511) / 512, 512>>>(edst, n_edges, n_nodes);

    int nblk = (n_nodes + 1023) / 1024;       // <= 128
    scanA_kernel<<<nblk, 1024>>>(n_nodes);
    scanB_kernel<<<1, 128>>>(nblk);
    scanC_kernel<<<nblk, 1024>>>(n_nodes);

    scatter_kernel<<<(n_edges + 511) / 512, 512>>>(esrc, edst, n_edges, n_nodes);

    spmm_gather_kernel<<<(n_nodes * 16 + 255) / 256, 256>>>(feat, n_nodes);

    gemm_kernel<<<(n_nodes + GR - 1) / GR, 256>>>(W, out, n_nodes);
}

// round 6
// speedup vs baseline: 2.2489x; 1.0534x over previous
#include <cuda_runtime.h>
#include <cstdint>

#define D 64
#define MAX_NODES 100000
#define MAX_EDGES 1600000
#define GR 64          // rows per GEMM block
#define SPAD 68        // smem row stride (floats)

typedef unsigned long long u64;

__device__ float g_neigh[MAX_NODES * D];
__device__ int   g_idx64;
__device__ int   g_cnt[MAX_NODES];       // in-degree histogram
__device__ int   g_start[MAX_NODES];     // exclusive prefix (CSR row offsets)
__device__ int   g_pos[MAX_NODES];       // scatter cursors
__device__ int   g_srcsorted[MAX_EDGES]; // src indices grouped by dst
__device__ int   g_bsum[128];            // per-scanA-block inclusive totals

#define FMA_F32X2(d, a, b, c) \
    asm("fma.rn.f32x2 %0, %1, %2, %3;" : "=l"(d) : "l"(a), "l"(b), "l"(c))
#define DUP_F32X2(d, v) \
    asm("mov.b64 %0, {%1, %1};" : "=l"(d) : "f"(v))

// ---------------------------------------------------------------------------
// Fused: detect index dtype (block 0) + zero g_cnt (all blocks).
// int64 buffers (values < 2^31) have every odd 32-bit word zero.
// ---------------------------------------------------------------------------
__global__ void detect_zero_kernel(const unsigned int* __restrict__ esrc_w,
                                   int n_edges, int n_nodes) {
    int i = blockIdx.x * 1024 + threadIdx.x;
    if (i < n_nodes) g_cnt[i] = 0;
    if (blockIdx.x == 0) {
        __shared__ int s_ok;
        if (threadIdx.x == 0) s_ok = 1;
        __syncthreads();
        int n_check = n_edges < 1024 ? n_edges : 1024;
        if (threadIdx.x < n_check && esrc_w[2 * threadIdx.x + 1] != 0u)
            atomicAnd(&s_ok, 0);
        __syncthreads();
        if (threadIdx.x == 0) g_idx64 = s_ok;
    }
}

__device__ __forceinline__ int load_idx(const void* p, int e, int n_nodes) {
    int v;
    if (g_idx64) v = (int)((const long long*)p)[e];
    else         v = ((const int*)p)[e];
    if (v < 0) v = 0;
    if (v >= n_nodes) v = n_nodes - 1;
    return v;
}

// ---------------------------------------------------------------------------
__global__ void hist_kernel(const void* __restrict__ edge_dst,
                            int n_edges, int n_nodes) {
    int e = blockIdx.x * blockDim.x + threadIdx.x;
    if (e >= n_edges) return;
    int d = load_idx(edge_dst, e, n_nodes);
    asm volatile("red.global.add.u32 [%0], %1;"
                 :: "l"(&g_cnt[d]), "r"(1) : "memory");
}

// ---------------------------------------------------------------------------
__device__ __forceinline__ int warp_incl_scan(int x, int lane) {
    #pragma unroll
    for (int off = 1; off < 32; off <<= 1) {
        int t = __shfl_up_sync(0xffffffffu, x, off);
        if (lane >= off) x += t;
    }
    return x;
}

// per-block exclusive scan; g_bsum[b] = block-b inclusive total
__global__ void scanA_kernel(int n) {
    __shared__ int wsum[32];
    int gid = blockIdx.x * 1024 + threadIdx.x;
    int lane = threadIdx.x & 31;
    int wid = threadIdx.x >> 5;
    int v = (gid < n) ? g_cnt[gid] : 0;
    int x = warp_incl_scan(v, lane);
    if (lane == 31) wsum[wid] = x;
    __syncthreads();
    if (wid == 0) wsum[lane] = warp_incl_scan(wsum[lane], lane);
    __syncthreads();
    int incl = x + (wid > 0 ? wsum[wid - 1] : 0);
    if (gid < n) g_start[gid] = incl - v;
    if (threadIdx.x == 1023) g_bsum[blockIdx.x] = incl;
}

// Fused scanB+scanC: each block redundantly reduces the <=128 block totals
// below its own block id, then adds that prefix to its 1024 elements.
__global__ void scan_fixup_kernel(int n) {
    __shared__ int warp_part[4];
    __shared__ int s_prefix;
    int t = threadIdx.x;
    if (t < 128) {
        int v = (t < blockIdx.x) ? g_bsum[t] : 0;
        #pragma unroll
        for (int off = 16; off > 0; off >>= 1)
            v += __shfl_xor_sync(0xffffffffu, v, off);
        if ((t & 31) == 0) warp_part[t >> 5] = v;
    }
    __syncthreads();
    if (t == 0) s_prefix = warp_part[0] + warp_part[1] + warp_part[2] + warp_part[3];
    __syncthreads();
    int gid = blockIdx.x * 1024 + t;
    if (gid < n) {
        int o = g_start[gid] + s_prefix;
        g_start[gid] = o;
        g_pos[gid] = o;
    }
}

// ---------------------------------------------------------------------------
__global__ void scatter_kernel(const void* __restrict__ edge_src,
                               const void* __restrict__ edge_dst,
                               int n_edges, int n_nodes) {
    int e = blockIdx.x * blockDim.x + threadIdx.x;
    if (e >= n_edges) return;
    int s = load_idx(edge_src, e, n_nodes);
    int d = load_idx(edge_dst, e, n_nodes);
    int pos = atomicAdd(&g_pos[d], 1);
    g_srcsorted[pos] = s;
}

// ---------------------------------------------------------------------------
// Fused SDDMM + SpMM gather: 16-lane group per dst node (2 nodes per warp).
// ---------------------------------------------------------------------------
__global__ __launch_bounds__(256) void spmm_gather_kernel(
        const float* __restrict__ feat, int n_nodes) {
    int g = (blockIdx.x * blockDim.x + threadIdx.x) >> 4;   // node id
    int lane = threadIdx.x & 15;
    unsigned hm = 0xFFFFu << (threadIdx.x & 16);            // own-half mask
    if (g >= n_nodes) return;

    int start = g_start[g];
    int end = start + g_cnt[g];

    const float4 hd = *reinterpret_cast<const float4*>(feat + (size_t)g * D + lane * 4);
    float4 acc = make_float4(0.f, 0.f, 0.f, 0.f);

    int i = start;
    for (; i + 1 < end; i += 2) {
        int s0 = g_srcsorted[i];
        int s1 = g_srcsorted[i + 1];
        const float4 h0 = *reinterpret_cast<const float4*>(feat + (size_t)s0 * D + lane * 4);
        const float4 h1 = *reinterpret_cast<const float4*>(feat + (size_t)s1 * D + lane * 4);
        float p0 = h0.x * hd.x + h0.y * hd.y + h0.z * hd.z + h0.w * hd.w;
        float p1 = h1.x * hd.x + h1.y * hd.y + h1.z * hd.z + h1.w * hd.w;
        p0 += __shfl_xor_sync(hm, p0, 8);
        p1 += __shfl_xor_sync(hm, p1, 8);
        p0 += __shfl_xor_sync(hm, p0, 4);
        p1 += __shfl_xor_sync(hm, p1, 4);
        p0 += __shfl_xor_sync(hm, p0, 2);
        p1 += __shfl_xor_sync(hm, p1, 2);
        p0 += __shfl_xor_sync(hm, p0, 1);
        p1 += __shfl_xor_sync(hm, p1, 1);
        acc.x += h0.x * p0 + h1.x * p1;
        acc.y += h0.y * p0 + h1.y * p1;
        acc.z += h0.z * p0 + h1.z * p1;
        acc.w += h0.w * p0 + h1.w * p1;
    }
    if (i < end) {
        int s0 = g_srcsorted[i];
        const float4 h0 = *reinterpret_cast<const float4*>(feat + (size_t)s0 * D + lane * 4);
        float p0 = h0.x * hd.x + h0.y * hd.y + h0.z * hd.z + h0.w * hd.w;
        p0 += __shfl_xor_sync(hm, p0, 8);
        p0 += __shfl_xor_sync(hm, p0, 4);
        p0 += __shfl_xor_sync(hm, p0, 2);
        p0 += __shfl_xor_sync(hm, p0, 1);
        acc.x += h0.x * p0;
        acc.y += h0.y * p0;
        acc.z += h0.z * p0;
        acc.w += h0.w * p0;
    }

    *reinterpret_cast<float4*>(g_neigh + (size_t)g * D + lane * 4) = acc;
}

// ---------------------------------------------------------------------------
// GEMM: out = neigh @ W.T, inner loop on packed f32x2 (FFMA2).
// acc pairs: accA[j] = cols (c, c+1), accB[j] = cols (c+2, c+3).
// ---------------------------------------------------------------------------
__global__ __launch_bounds__(256) void gemm_kernel(const float* __restrict__ W,
                                                   float* __restrict__ out,
                                                   int n_rows) {
    __shared__ float sWt[D][SPAD];
    __shared__ float sN[GR][SPAD];

    int tid = threadIdx.x;
    int tx = tid & 15;
    int ty = tid >> 4;

    #pragma unroll
    for (int it = 0; it < 16; it++) {
        int idx = tid + 256 * it;
        int o = idx >> 6;
        int k = idx & 63;
        sWt[k][o] = W[idx];
    }

    int row0 = blockIdx.x * GR;
    #pragma unroll
    for (int it = 0; it < 4; it++) {
        int idx = tid + 256 * it;
        int r = idx >> 4;
        int c4 = idx & 15;
        int row = row0 + r;
        float4 v = make_float4(0.f, 0.f, 0.f, 0.f);
        if (row < n_rows)
            v = *reinterpret_cast<const float4*>(g_neigh + (size_t)row * D + c4 * 4);
        *reinterpret_cast<float4*>(&sN[r][c4 * 4]) = v;
    }
    __syncthreads();

    u64 accA[4], accB[4];
    #pragma unroll
    for (int j = 0; j < 4; j++) { accA[j] = 0ull; accB[j] = 0ull; }

    int c = tx * 4;
    #pragma unroll
    for (int k4 = 0; k4 < D / 4; k4++) {
        int k = k4 * 4;
        // each LDS.128 gives two packed f32x2 (lo = cols c,c+1; hi = c+2,c+3)
        const ulonglong2 l0 = *reinterpret_cast<const ulonglong2*>(&sWt[k + 0][c]);
        const ulonglong2 l1 = *reinterpret_cast<const ulonglong2*>(&sWt[k + 1][c]);
        const ulonglong2 l2 = *reinterpret_cast<const ulonglong2*>(&sWt[k + 2][c]);
        const ulonglong2 l3 = *reinterpret_cast<const ulonglong2*>(&sWt[k + 3][c]);
        #pragma unroll
        for (int j = 0; j < 4; j++) {
            const float4 nb = *reinterpret_cast<const float4*>(&sN[ty + 16 * j][k]);
            u64 dx, dy, dz, dw;
            DUP_F32X2(dx, nb.x);
            DUP_F32X2(dy, nb.y);
            DUP_F32X2(dz, nb.z);
            DUP_F32X2(dw, nb.w);
            FMA_F32X2(accA[j], dx, l0.x, accA[j]);
            FMA_F32X2(accB[j], dx, l0.y, accB[j]);
            FMA_F32X2(accA[j], dy, l1.x, accA[j]);
            FMA_F32X2(accB[j], dy, l1.y, accB[j]);
            FMA_F32X2(accA[j], dz, l2.x, accA[j]);
            FMA_F32X2(accB[j], dz, l2.y, accB[j]);
            FMA_F32X2(accA[j], dw, l3.x, accA[j]);
            FMA_F32X2(accB[j], dw, l3.y, accB[j]);
        }
    }

    #pragma unroll
    for (int j = 0; j < 4; j++) {
        int row = row0 + ty + 16 * j;
        if (row < n_rows) {
            ulonglong2 o;
            o.x = accA[j];
            o.y = accB[j];
            *reinterpret_cast<ulonglong2*>(out + (size_t)row * D + c) = o;
        }
    }
}

// ---------------------------------------------------------------------------
extern "C" void kernel_launch(void* const* d_in, const int* in_sizes, int n_in,
                              void* d_out, int out_size) {
    const float* feat = (const float*)d_in[0];
    const void*  esrc = d_in[1];
    const void*  edst = d_in[2];
    const float* W    = (const float*)d_in[3];
    float*       out  = (float*)d_out;

    int n_nodes = in_sizes[0] / D;
    int n_edges = in_sizes[1];

    int nblk = (n_nodes + 1023) / 1024;       // <= 128

    detect_zero_kernel<<<nblk, 1024>>>((const unsigned int*)esrc, n_edges, n_nodes);
    hist_kernel<<<(n_edges + 511) / 512, 512>>>(edst, n_edges, n_nodes);
    scanA_kernel<<<nblk, 1024>>>(n_nodes);
    scan_fixup_kernel<<<nblk, 1024>>>(n_nodes);
    scatter_kernel<<<(n_edges + 511) / 512, 512>>>(esrc, edst, n_edges, n_nodes);
    spmm_gather_kernel<<<(n_nodes * 16 + 255) / 256, 256>>>(feat, n_nodes);
    gemm_kernel<<<(n_nodes + GR - 1) / GR, 256>>>(W, out, n_nodes);
}